// round 2
// baseline (speedup 1.0000x reference)
#include <cuda_runtime.h>
#include <cuda_bf16.h>
#include <math.h>

// ---------------------------------------------------------------------------
// Problem constants (fixed by the dataset)
// ---------------------------------------------------------------------------
#define NMAX 50000
#define EDGEMAX 300000
#define ETOT (EDGEMAX + NMAX)   // edges + self loops
#define GDIM 405

// ---------------------------------------------------------------------------
// Device scratch (allocation-free rule: __device__ globals)
// ---------------------------------------------------------------------------
__device__ float g_t1  [NMAX * 256];    // encoder intermediate
__device__ float g_henc[NMAX * 256];    // encoder output
__device__ float g_A   [NMAX * 1024];   // hW1 / h1
__device__ float g_B   [NMAX * 1024];   // aggr1
__device__ float g_C   [NMAX * 1024];   // res1
__device__ float g_D   [NMAX * 192];    // hW2 / h2
__device__ float g_E2  [NMAX * 192];    // aggr2
__device__ float g_F   [NMAX * 192];    // res2
__device__ float g_G   [NMAX * 128];    // hW3 / h3
__device__ float g_Hh  [NMAX * 128];    // aggr3
__device__ float g_I   [NMAX * 128];    // res3
__device__ float g_J   [NMAX * 64];     // mlp hidden
__device__ float g_asrc[NMAX * 4];
__device__ float g_adst[NMAX * 4];
__device__ float g_emax[NMAX * 4];
__device__ float g_den [NMAX * 4];
__device__ float g_ebuf[ETOT * 4];

// ---------------------------------------------------------------------------
// SGEMM: C[M,Nc] = A[M,K] @ B[K,Nc] (+bias) (+relu)
// 128x128 block tile, BK=8, 256 threads, 8x8 per-thread micro-tile.
// ---------------------------------------------------------------------------
__global__ __launch_bounds__(256)
void sgemm_kernel(const float* __restrict__ A, const float* __restrict__ B,
                  const float* __restrict__ bias, float* __restrict__ Cout,
                  int M, int Nc, int K, int act)
{
    const int BM = 128, BN = 128, BK = 8, TM = 8, TN = 8;
    __shared__ float As[BK][BM];
    __shared__ float Bs[BK][BN];

    const int tid  = threadIdx.x;
    const int brow = blockIdx.y * BM;
    const int bcol = blockIdx.x * BN;
    const int tx = tid & 15;          // 0..15
    const int ty = tid >> 4;          // 0..15

    float acc[TM][TN];
#pragma unroll
    for (int i = 0; i < TM; i++)
#pragma unroll
        for (int j = 0; j < TN; j++) acc[i][j] = 0.f;

    const int arow  = tid >> 1;        // 0..127
    const int acol  = (tid & 1) * 4;   // 0 or 4
    const int brow2 = tid >> 5;        // 0..7
    const int bcol2 = (tid & 31) * 4;  // 0..124

    for (int kt = 0; kt < K; kt += BK) {
#pragma unroll
        for (int i = 0; i < 4; i++) {
            int gk = kt + acol + i;
            int gm = brow + arow;
            As[acol + i][arow] = (gm < M && gk < K) ? A[(long long)gm * K + gk] : 0.f;
        }
#pragma unroll
        for (int i = 0; i < 4; i++) {
            int gk = kt + brow2;
            int gn = bcol + bcol2 + i;
            Bs[brow2][bcol2 + i] = (gk < K && gn < Nc) ? B[(long long)gk * Nc + gn] : 0.f;
        }
        __syncthreads();
#pragma unroll
        for (int kk = 0; kk < BK; kk++) {
            float ra[TM], rb[TN];
#pragma unroll
            for (int i = 0; i < TM; i++) ra[i] = As[kk][ty * TM + i];
#pragma unroll
            for (int j = 0; j < TN; j++) rb[j] = Bs[kk][tx * TN + j];
#pragma unroll
            for (int i = 0; i < TM; i++)
#pragma unroll
                for (int j = 0; j < TN; j++) acc[i][j] += ra[i] * rb[j];
        }
        __syncthreads();
    }

#pragma unroll
    for (int i = 0; i < TM; i++) {
        int gm = brow + ty * TM + i;
        if (gm >= M) continue;
#pragma unroll
        for (int j = 0; j < TN; j++) {
            int gn = bcol + tx * TN + j;
            if (gn >= Nc) continue;
            float v = acc[i][j];
            if (bias) v += bias[gn];
            if (act == 1) v = fmaxf(v, 0.f);
            Cout[(long long)gm * Nc + gn] = v;
        }
    }
}

// ---------------------------------------------------------------------------
// LayerNorm(D=256) + ReLU, in place. One block (256 threads) per row.
// ---------------------------------------------------------------------------
__global__ __launch_bounds__(256)
void ln_relu_kernel(float* __restrict__ x, const float* __restrict__ g,
                    const float* __restrict__ b)
{
    const int row = blockIdx.x;
    float* p = x + (long long)row * 256;
    float v = p[threadIdx.x];

    __shared__ float ws[8];
    const int w = threadIdx.x >> 5, l = threadIdx.x & 31;

    float s = v;
#pragma unroll
    for (int o = 16; o; o >>= 1) s += __shfl_xor_sync(0xffffffffu, s, o);
    if (l == 0) ws[w] = s;
    __syncthreads();
    float m = 0.f;
#pragma unroll
    for (int i = 0; i < 8; i++) m += ws[i];
    m *= (1.f / 256.f);
    __syncthreads();

    float dv = v - m;
    float q = dv * dv;
#pragma unroll
    for (int o = 16; o; o >>= 1) q += __shfl_xor_sync(0xffffffffu, q, o);
    if (l == 0) ws[w] = q;
    __syncthreads();
    float var = 0.f;
#pragma unroll
    for (int i = 0; i < 8; i++) var += ws[i];
    var *= (1.f / 256.f);

    float y = dv * rsqrtf(var + 1e-5f) * g[threadIdx.x] + b[threadIdx.x];
    p[threadIdx.x] = fmaxf(y, 0.f);
}

// ---------------------------------------------------------------------------
// Attention dot products: asrc[n,h] = <hW[n,h,:], att_src[h,:]>, same for adst.
// One warp per (n,h).
// ---------------------------------------------------------------------------
__global__ __launch_bounds__(256)
void att_dots_kernel(const float* __restrict__ hW,
                     const float* __restrict__ att_src,
                     const float* __restrict__ att_dst,
                     float* __restrict__ asrc, float* __restrict__ adst,
                     int N, int H, int C)
{
    long long warp = ((long long)blockIdx.x * blockDim.x + threadIdx.x) >> 5;
    int lane = threadIdx.x & 31;
    if (warp >= (long long)N * H) return;
    int h = (int)(warp % H);
    const float* hp = hW + warp * C;
    const float* as = att_src + h * C;
    const float* ad = att_dst + h * C;
    float s = 0.f, d2 = 0.f;
    for (int c = lane; c < C; c += 32) {
        float hv = hp[c];
        s  += hv * as[c];
        d2 += hv * ad[c];
    }
#pragma unroll
    for (int o = 16; o; o >>= 1) {
        s  += __shfl_down_sync(0xffffffffu, s, o);
        d2 += __shfl_down_sync(0xffffffffu, d2, o);
    }
    if (lane == 0) { asrc[warp] = s; adst[warp] = d2; }
}

// ---------------------------------------------------------------------------
// float atomic max via sign-split int/uint trick (emax initialized to -inf)
// ---------------------------------------------------------------------------
__device__ __forceinline__ void atomicMaxF(float* addr, float val)
{
    if (val >= 0.f) atomicMax((int*)addr, __float_as_int(val));
    else            atomicMin((unsigned int*)addr, __float_as_uint(val));
}

__device__ __forceinline__ void edge_ends(const int* __restrict__ srcA,
                                          const int* __restrict__ dstA,
                                          long long e, int E, int& s, int& d)
{
    if (e < E) { s = srcA[e]; d = dstA[e]; }
    else       { s = d = (int)(e - E); }
}

// Pass A: e = leaky_relu(asrc[src]+adst[dst]); ebuf = e; atomicMax emax[dst].
__global__ __launch_bounds__(256)
void edge_logits_kernel(const int* __restrict__ srcA,
                        const int* __restrict__ dstA, int E, int N, int H,
                        const float* __restrict__ asrc,
                        const float* __restrict__ adst,
                        float* __restrict__ ebuf, float* __restrict__ emax)
{
    long long i = (long long)blockIdx.x * blockDim.x + threadIdx.x;
    long long tot = (long long)(E + N) * H;
    if (i >= tot) return;
    long long e = i / H; int h = (int)(i % H);
    int s, d; edge_ends(srcA, dstA, e, E, s, d);
    float v = asrc[(long long)s * H + h] + adst[(long long)d * H + h];
    v = v > 0.f ? v : 0.2f * v;
    ebuf[i] = v;
    atomicMaxF(&emax[(long long)d * H + h], v);
}

// Pass B: ee = exp(e - emax[dst]); ebuf = ee; atomicAdd denom[dst].
__global__ __launch_bounds__(256)
void edge_exp_kernel(const int* __restrict__ srcA,
                     const int* __restrict__ dstA, int E, int N, int H,
                     float* __restrict__ ebuf, const float* __restrict__ emax,
                     float* __restrict__ den)
{
    long long i = (long long)blockIdx.x * blockDim.x + threadIdx.x;
    long long tot = (long long)(E + N) * H;
    if (i >= tot) return;
    long long e = i / H; int h = (int)(i % H);
    int s, d; edge_ends(srcA, dstA, e, E, s, d);
    float ee = expf(ebuf[i] - emax[(long long)d * H + h]);
    ebuf[i] = ee;
    atomicAdd(&den[(long long)d * H + h], ee);
}

// Vector red.global.add.v4.f32 (sm_90+): 4 floats per reduction op.
__device__ __forceinline__ void redAddV4(float* addr, float4 v)
{
    asm volatile("red.global.add.v4.f32 [%0], {%1, %2, %3, %4};"
                 :: "l"(addr), "f"(v.x), "f"(v.y), "f"(v.z), "f"(v.w)
                 : "memory");
}

// Pass C: out[dst,h,:] += alpha * hW[src,h,:]. One warp per (edge, head).
// C is a multiple of 4; rows 16B-aligned. float4 gather + v4 reduction.
__global__ __launch_bounds__(256)
void edge_aggr_kernel(const int* __restrict__ srcA,
                      const int* __restrict__ dstA, int E, int N, int H, int C,
                      const float* __restrict__ ebuf,
                      const float* __restrict__ den,
                      const float* __restrict__ hW, float* __restrict__ out)
{
    long long warp = ((long long)blockIdx.x * blockDim.x + threadIdx.x) >> 5;
    int lane = threadIdx.x & 31;
    long long tot = (long long)(E + N) * H;
    if (warp >= tot) return;
    long long e = warp / H; int h = (int)(warp % H);
    int s, d; edge_ends(srcA, dstA, e, E, s, d);
    float alpha = ebuf[warp] / (den[(long long)d * H + h] + 1e-16f);
    const float4* hp = (const float4*)(hW  + ((long long)s * H + h) * C);
    float*        op = out + ((long long)d * H + h) * C;
    int C4 = C >> 2;
    for (int c = lane; c < C4; c += 32) {
        float4 v = hp[c];
        v.x *= alpha; v.y *= alpha; v.z *= alpha; v.w *= alpha;
        redAddV4(op + c * 4, v);
    }
}

// ---------------------------------------------------------------------------
// fill
// ---------------------------------------------------------------------------
__global__ void fill_kernel(float* __restrict__ p, long long n, float v)
{
    long long i = (long long)blockIdx.x * blockDim.x + threadIdx.x;
    if (i < n) p[i] = v;
}

// out = elu(aggr + bias[j]) + res
__global__ void elu_bias_res_kernel(const float* __restrict__ aggr,
                                    const float* __restrict__ bias,
                                    const float* __restrict__ res,
                                    float* __restrict__ out, long long N, int D)
{
    long long i = (long long)blockIdx.x * blockDim.x + threadIdx.x;
    if (i >= N * D) return;
    int j = (int)(i % D);
    float v = aggr[i] + bias[j];
    v = v > 0.f ? v : (expf(v) - 1.f);
    out[i] = v + res[i];
}

// Final 64->2 head: one thread per node.
__global__ void mlp2_kernel(const float* __restrict__ J, const float* __restrict__ w,
                            const float* __restrict__ b, float* __restrict__ out, int N)
{
    int n = blockIdx.x * blockDim.x + threadIdx.x;
    if (n >= N) return;
    const float* r = J + (long long)n * 64;
    float s0 = b[0], s1 = b[1];
#pragma unroll
    for (int k = 0; k < 64; k++) {
        float v = r[k];
        s0 += v * w[k * 2 + 0];
        s1 += v * w[k * 2 + 1];
    }
    out[(long long)n * 2 + 0] = s0;
    out[(long long)n * 2 + 1] = s1;
}

// ---------------------------------------------------------------------------
// Host orchestration
// ---------------------------------------------------------------------------
static inline void run_sgemm(const float* A, const float* B, const float* bias,
                             float* C, int M, int Nc, int K, int act)
{
    dim3 grid((Nc + 127) / 128, (M + 127) / 128);
    sgemm_kernel<<<grid, 256>>>(A, B, bias, C, M, Nc, K, act);
}

static inline void run_fill(float* p, long long n, float v)
{
    long long blocks = (n + 255) / 256;
    fill_kernel<<<(unsigned)blocks, 256>>>(p, n, v);
}

static void run_gat_edges(const int* srcA, const int* dstA,
                          int E, int N, int H, int C,
                          const float* hW, const float* att_src, const float* att_dst,
                          float* asrc, float* adst, float* emax, float* den,
                          float* ebuf, float* out)
{
    // attention scalars
    {
        long long warps = (long long)N * H;
        long long blocks = (warps * 32 + 255) / 256;
        att_dots_kernel<<<(unsigned)blocks, 256>>>(hW, att_src, att_dst, asrc, adst, N, H, C);
    }
    run_fill(emax, (long long)N * H, -INFINITY);
    run_fill(den,  (long long)N * H, 0.f);
    run_fill(out,  (long long)N * H * C, 0.f);

    long long tot = (long long)(E + N) * H;
    {
        long long blocks = (tot + 255) / 256;
        edge_logits_kernel<<<(unsigned)blocks, 256>>>(srcA, dstA, E, N, H, asrc, adst, ebuf, emax);
        edge_exp_kernel<<<(unsigned)blocks, 256>>>(srcA, dstA, E, N, H, ebuf, emax, den);
    }
    {
        long long blocks = (tot * 32 + 255) / 256;
        edge_aggr_kernel<<<(unsigned)blocks, 256>>>(srcA, dstA, E, N, H, C, ebuf, den, hW, out);
    }
}

extern "C" void kernel_launch(void* const* d_in, const int* in_sizes, int n_in,
                              void* d_out, int out_size)
{
    // inputs in metadata order
    const float* x      = (const float*)d_in[0];
    const int*   ei     = (const int*)d_in[1];      // edge_index downcast to int32
    const float* enc_w1 = (const float*)d_in[2];
    const float* enc_b1 = (const float*)d_in[3];
    const float* ln1_g  = (const float*)d_in[4];
    const float* ln1_b  = (const float*)d_in[5];
    const float* enc_w2 = (const float*)d_in[6];
    const float* enc_b2 = (const float*)d_in[7];
    const float* ln2_g  = (const float*)d_in[8];
    const float* ln2_b  = (const float*)d_in[9];
    const float* w1       = (const float*)d_in[10];
    const float* att_src1 = (const float*)d_in[11];
    const float* att_dst1 = (const float*)d_in[12];
    const float* bias1    = (const float*)d_in[13];
    const float* res1_w   = (const float*)d_in[14];
    const float* res1_b   = (const float*)d_in[15];
    const float* w2       = (const float*)d_in[16];
    const float* att_src2 = (const float*)d_in[17];
    const float* att_dst2 = (const float*)d_in[18];
    const float* bias2    = (const float*)d_in[19];
    const float* res2_w   = (const float*)d_in[20];
    const float* res2_b   = (const float*)d_in[21];
    const float* w3       = (const float*)d_in[22];
    const float* att_src3 = (const float*)d_in[23];
    const float* att_dst3 = (const float*)d_in[24];
    const float* bias3    = (const float*)d_in[25];
    const float* res3_w   = (const float*)d_in[26];
    const float* res3_b   = (const float*)d_in[27];
    const float* mlp_w1   = (const float*)d_in[28];
    const float* mlp_b1   = (const float*)d_in[29];
    const float* mlp_w2   = (const float*)d_in[30];
    const float* mlp_b2   = (const float*)d_in[31];

    const int N = in_sizes[0] / GDIM;
    const int E = in_sizes[1] / 2;
    const int* srcA = ei;
    const int* dstA = ei + E;

    float *t1, *henc, *A, *B, *C, *D, *E2, *F, *G, *Hh, *I, *J;
    float *asrc, *adst, *emax, *den, *ebuf;
    cudaGetSymbolAddress((void**)&t1,   g_t1);
    cudaGetSymbolAddress((void**)&henc, g_henc);
    cudaGetSymbolAddress((void**)&A,    g_A);
    cudaGetSymbolAddress((void**)&B,    g_B);
    cudaGetSymbolAddress((void**)&C,    g_C);
    cudaGetSymbolAddress((void**)&D,    g_D);
    cudaGetSymbolAddress((void**)&E2,   g_E2);
    cudaGetSymbolAddress((void**)&F,    g_F);
    cudaGetSymbolAddress((void**)&G,    g_G);
    cudaGetSymbolAddress((void**)&Hh,   g_Hh);
    cudaGetSymbolAddress((void**)&I,    g_I);
    cudaGetSymbolAddress((void**)&J,    g_J);
    cudaGetSymbolAddress((void**)&asrc, g_asrc);
    cudaGetSymbolAddress((void**)&adst, g_adst);
    cudaGetSymbolAddress((void**)&emax, g_emax);
    cudaGetSymbolAddress((void**)&den,  g_den);
    cudaGetSymbolAddress((void**)&ebuf, g_ebuf);

    // ---- JointEncoder ----
    run_sgemm(x, enc_w1, enc_b1, t1, N, 256, GDIM, 0);
    ln_relu_kernel<<<N, 256>>>(t1, ln1_g, ln1_b);
    run_sgemm(t1, enc_w2, enc_b2, henc, N, 256, 256, 0);
    ln_relu_kernel<<<N, 256>>>(henc, ln2_g, ln2_b);

    // ---- Block 1: GAT 256 -> 4x256 (concat) ----
    run_sgemm(henc, w1, nullptr, A, N, 1024, 256, 0);                  // hW1
    run_gat_edges(srcA, dstA, E, N, 4, 256, A, att_src1, att_dst1,
                  asrc, adst, emax, den, ebuf, B);                     // aggr1 -> B
    run_sgemm(henc, res1_w, res1_b, C, N, 1024, 256, 0);               // res1
    {
        long long n = (long long)N * 1024;
        elu_bias_res_kernel<<<(unsigned)((n + 255) / 256), 256>>>(B, bias1, C, A, N, 1024); // h1 -> A
    }

    // ---- Block 2: GAT 1024 -> 2x96 (concat) ----
    run_sgemm(A, w2, nullptr, D, N, 192, 1024, 0);                     // hW2
    run_gat_edges(srcA, dstA, E, N, 2, 96, D, att_src2, att_dst2,
                  asrc, adst, emax, den, ebuf, E2);                    // aggr2
    run_sgemm(A, res2_w, res2_b, F, N, 192, 1024, 0);                  // res2
    {
        long long n = (long long)N * 192;
        elu_bias_res_kernel<<<(unsigned)((n + 255) / 256), 256>>>(E2, bias2, F, D, N, 192); // h2 -> D
    }

    // ---- Block 3: GAT 192 -> 1x128 (mean over 1 head == identity) ----
    run_sgemm(D, w3, nullptr, G, N, 128, 192, 0);                      // hW3
    run_gat_edges(srcA, dstA, E, N, 1, 128, G, att_src3, att_dst3,
                  asrc, adst, emax, den, ebuf, Hh);                    // aggr3
    run_sgemm(D, res3_w, res3_b, I, N, 128, 192, 0);                   // res3
    {
        long long n = (long long)N * 128;
        elu_bias_res_kernel<<<(unsigned)((n + 255) / 256), 256>>>(Hh, bias3, I, G, N, 128); // h3 -> G
    }

    // ---- MLP head ----
    run_sgemm(G, mlp_w1, mlp_b1, J, N, 64, 128, 1);                    // relu
    mlp2_kernel<<<(N + 255) / 256, 256>>>(J, mlp_w2, mlp_b2, (float*)d_out, N);
}

// round 4
// speedup vs baseline: 2.2605x; 2.2605x over previous
#include <cuda_runtime.h>
#include <cuda_bf16.h>
#include <math.h>

// ---------------------------------------------------------------------------
// Problem constants
// ---------------------------------------------------------------------------
#define NMAX 50000
#define EDGEMAX 300000
#define ETOT (EDGEMAX + NMAX)
#define GDIM 405

// ---------------------------------------------------------------------------
// Device scratch
// ---------------------------------------------------------------------------
__device__ float g_t1  [NMAX * 256];
__device__ float g_henc[NMAX * 256];
__device__ float g_A   [NMAX * 1024];   // hW1 / h1
__device__ float g_B   [NMAX * 1024];   // aggr1
__device__ float g_D   [NMAX * 192];    // hW2 / h2
__device__ float g_E2  [NMAX * 192];    // aggr2
__device__ float g_G   [NMAX * 128];    // hW3 / h3
__device__ float g_Hh  [NMAX * 128];    // aggr3
__device__ float g_J   [NMAX * 64];
__device__ float g_asrc[NMAX * 4];
__device__ float g_adst[NMAX * 4];
__device__ float g_emax[NMAX * 4];
__device__ float g_den [NMAX * 4];
__device__ float g_ebuf[ETOT * 4];
// bf16 split buffers
__device__ __nv_bfloat16 g_sAhi[NMAX * 1024];
__device__ __nv_bfloat16 g_sAlo[NMAX * 1024];
__device__ __nv_bfloat16 g_sBhi[1024 * 1024];
__device__ __nv_bfloat16 g_sBlo[1024 * 1024];

// ---------------------------------------------------------------------------
// Baseline-PTX helpers (all sm_80-level: work on plain sm_103 target)
// ---------------------------------------------------------------------------
__device__ __forceinline__ unsigned smem_u32(const void* p) {
    unsigned a;
    asm("{ .reg .u64 t; cvta.to.shared.u64 t, %1; cvt.u32.u64 %0, t; }"
        : "=r"(a) : "l"(p));
    return a;
}
__device__ __forceinline__ void cp16(unsigned d, const void* s, unsigned srcsz) {
    asm volatile("cp.async.cg.shared.global [%0], [%1], 16, %2;"
                 :: "r"(d), "l"(s), "r"(srcsz) : "memory");
}
__device__ __forceinline__ void cp_commit() {
    asm volatile("cp.async.commit_group;" ::: "memory");
}
__device__ __forceinline__ void ldsm4(unsigned r[4], unsigned addr) {
    asm volatile("ldmatrix.sync.aligned.m8n8.x4.shared.b16 {%0,%1,%2,%3}, [%4];"
                 : "=r"(r[0]), "=r"(r[1]), "=r"(r[2]), "=r"(r[3]) : "r"(addr));
}
__device__ __forceinline__ void mma16816(float c[4], const unsigned a[4],
                                         const unsigned b0, const unsigned b1) {
    asm volatile(
        "mma.sync.aligned.m16n8k16.row.col.f32.bf16.bf16.f32 "
        "{%0,%1,%2,%3}, {%4,%5,%6,%7}, {%8,%9}, {%0,%1,%2,%3};"
        : "+f"(c[0]), "+f"(c[1]), "+f"(c[2]), "+f"(c[3])
        : "r"(a[0]), "r"(a[1]), "r"(a[2]), "r"(a[3]), "r"(b0), "r"(b1));
}

// ---------------------------------------------------------------------------
// Split kernels: fp32 -> (hi, lo) bf16
// ---------------------------------------------------------------------------
__device__ __forceinline__ void split4(const float v[4],
                                       unsigned long long& hp, unsigned long long& lp) {
    unsigned long long h = 0, l = 0;
#pragma unroll
    for (int j = 0; j < 4; j++) {
        __nv_bfloat16 hb = __float2bfloat16(v[j]);
        __nv_bfloat16 lb = __float2bfloat16(v[j] - __bfloat162float(hb));
        h |= (unsigned long long)__bfloat16_as_ushort(hb) << (16 * j);
        l |= (unsigned long long)__bfloat16_as_ushort(lb) << (16 * j);
    }
    hp = h; lp = l;
}

__global__ void split_a_kernel(const float* __restrict__ X,
                               __nv_bfloat16* __restrict__ Hi,
                               __nv_bfloat16* __restrict__ Lo,
                               int M, int K, int Kpad)
{
    long long i = (long long)blockIdx.x * blockDim.x + threadIdx.x;
    long long tot = (long long)M * (Kpad >> 2);
    if (i >= tot) return;
    int k4 = (int)(i % (Kpad >> 2));
    long long row = i / (Kpad >> 2);
    float v[4];
#pragma unroll
    for (int j = 0; j < 4; j++) {
        int kk = 4 * k4 + j;
        v[j] = (kk < K) ? X[row * K + kk] : 0.f;
    }
    unsigned long long hp, lp;
    split4(v, hp, lp);
    *(unsigned long long*)(Hi + row * Kpad + 4 * k4) = hp;
    *(unsigned long long*)(Lo + row * Kpad + 4 * k4) = lp;
}

__global__ void split_bt_kernel(const float* __restrict__ B,
                                __nv_bfloat16* __restrict__ Hi,
                                __nv_bfloat16* __restrict__ Lo,
                                int K, int Nc, int Kpad)
{
    long long i = (long long)blockIdx.x * blockDim.x + threadIdx.x;
    long long tot = (long long)Nc * (Kpad >> 2);
    if (i >= tot) return;
    int n  = (int)(i % Nc);
    int k4 = (int)(i / Nc);
    float v[4];
#pragma unroll
    for (int j = 0; j < 4; j++) {
        int kk = 4 * k4 + j;
        v[j] = (kk < K) ? B[(long long)kk * Nc + n] : 0.f;
    }
    unsigned long long hp, lp;
    split4(v, hp, lp);
    *(unsigned long long*)(Hi + (long long)n * Kpad + 4 * k4) = hp;
    *(unsigned long long*)(Lo + (long long)n * Kpad + 4 * k4) = lp;
}

// ---------------------------------------------------------------------------
// Tensor-core GEMM via mma.sync bf16 (3-term split, fp32 accum)
//   C[M,Nc] = A[M,Kpad] @ B[Nc,Kpad]^T  (B pre-transposed to [n,k])
// Tile 128x128x32, 256 threads, 8 warps (4x2), warp tile 32x64.
// smem rows padded to 80B (conflict-free ldmatrix), cp.async double buffer.
// act: 0 = (+bias), 1 = relu(+bias), 2 = elu(aggr+gat_bias) + acc + bias
// ---------------------------------------------------------------------------
#define ROWB 80
#define MATB (128 * ROWB)          // 10240
#define OFF_AH 0
#define OFF_AL (1 * MATB)
#define OFF_BH (2 * MATB)
#define OFF_BL (3 * MATB)
#define BUFB (4 * MATB)            // 40960
#define TC_SMEM (2 * BUFB)         // 81920

__global__ __launch_bounds__(256)
void mma_gemm_kernel(const __nv_bfloat16* __restrict__ Ahi,
                     const __nv_bfloat16* __restrict__ Alo,
                     const __nv_bfloat16* __restrict__ Bhi,
                     const __nv_bfloat16* __restrict__ Blo,
                     float* __restrict__ C,
                     int M, int Nc, int Kpad,
                     const float* __restrict__ bias, int act,
                     const float* __restrict__ aggr,
                     const float* __restrict__ gat_bias)
{
    extern __shared__ char smem[];
    const unsigned sb = smem_u32(smem);
    const int tid = threadIdx.x;
    const int wid = tid >> 5, lane = tid & 31;
    const int bm = blockIdx.y * 128;
    const int bn = blockIdx.x * 128;
    const int Ntile = min(128, Nc - bn);
    const int warp_m = wid & 3;      // 0..3  -> rows warp_m*32
    const int warp_n = wid >> 2;     // 0..1  -> cols warp_n*64
    const int NCH = Kpad >> 5;

    float acc[2][8][4];
#pragma unroll
    for (int mi = 0; mi < 2; mi++)
#pragma unroll
        for (int ni = 0; ni < 8; ni++)
#pragma unroll
            for (int q = 0; q < 4; q++) acc[mi][ni][q] = 0.f;

    // loader mapping: thread -> (row, 2 chunks)
    const int lrow = tid >> 1;            // 0..127
    const int lc0  = (tid & 1) * 2;       // 0 or 2

    const long long gmA = bm + lrow;
    const unsigned okA = (gmA < M) ? 16u : 0u;
    const long long rowA = (okA ? gmA : 0) * (long long)Kpad;
    const unsigned okB = (lrow < Ntile) ? 16u : 0u;
    const long long rowB = (long long)(okB ? (bn + lrow) : 0) * Kpad;

#define LOAD_CHUNK(c)                                                          \
    do {                                                                       \
        const unsigned bd = sb + ((c) & 1) * BUFB;                             \
        const long long kb = (long long)(c) * 32;                              \
        _Pragma("unroll")                                                      \
        for (int j = 0; j < 2; j++) {                                          \
            const int ch = lc0 + j;                                            \
            const unsigned so = lrow * ROWB + ch * 16;                         \
            const long long go = kb + ch * 8;                                  \
            cp16(bd + OFF_AH + so, Ahi + rowA + go, okA);                      \
            cp16(bd + OFF_AL + so, Alo + rowA + go, okA);                      \
            cp16(bd + OFF_BH + so, Bhi + rowB + go, okB);                      \
            cp16(bd + OFF_BL + so, Blo + rowB + go, okB);                      \
        }                                                                      \
    } while (0)

    LOAD_CHUNK(0);
    cp_commit();

    for (int c = 0; c < NCH; c++) {
        if (c + 1 < NCH) {
            LOAD_CHUNK(c + 1);
            cp_commit();
            asm volatile("cp.async.wait_group 1;" ::: "memory");
        } else {
            asm volatile("cp.async.wait_group 0;" ::: "memory");
        }
        __syncthreads();

        const unsigned bd = sb + (c & 1) * BUFB;
#pragma unroll
        for (int ks = 0; ks < 2; ks++) {
            unsigned ah[2][4], al[2][4];
#pragma unroll
            for (int mi = 0; mi < 2; mi++) {
                const int row = warp_m * 32 + mi * 16 + (lane & 15);
                const int ch  = ks * 2 + (lane >> 4);
                const unsigned off = row * ROWB + ch * 16;
                ldsm4(ah[mi], bd + OFF_AH + off);
                ldsm4(al[mi], bd + OFF_AL + off);
            }
            unsigned bh[8][2], bl[8][2];
#pragma unroll
            for (int np = 0; np < 4; np++) {
                const int row = warp_n * 64 + np * 16 + ((lane >> 4) & 1) * 8 + (lane & 7);
                const int ch  = ks * 2 + ((lane >> 3) & 1);
                const unsigned off = row * ROWB + ch * 16;
                unsigned r[4];
                ldsm4(r, bd + OFF_BH + off);
                bh[2 * np][0] = r[0]; bh[2 * np][1] = r[1];
                bh[2 * np + 1][0] = r[2]; bh[2 * np + 1][1] = r[3];
                ldsm4(r, bd + OFF_BL + off);
                bl[2 * np][0] = r[0]; bl[2 * np][1] = r[1];
                bl[2 * np + 1][0] = r[2]; bl[2 * np + 1][1] = r[3];
            }
#pragma unroll
            for (int mi = 0; mi < 2; mi++)
#pragma unroll
                for (int ni = 0; ni < 8; ni++) {
                    mma16816(acc[mi][ni], ah[mi], bh[ni][0], bh[ni][1]);
                    mma16816(acc[mi][ni], ah[mi], bl[ni][0], bl[ni][1]);
                    mma16816(acc[mi][ni], al[mi], bh[ni][0], bh[ni][1]);
                }
        }
        __syncthreads();
    }

    // epilogue
#pragma unroll
    for (int mi = 0; mi < 2; mi++) {
#pragma unroll
        for (int half = 0; half < 2; half++) {
            const long long gm = bm + warp_m * 32 + mi * 16 + (lane >> 2) + half * 8;
            if (gm >= M) continue;
#pragma unroll
            for (int ni = 0; ni < 8; ni++) {
                const int gn = bn + warp_n * 64 + ni * 8 + (lane & 3) * 2;
                if (gn >= Nc) continue;
                float v0 = acc[mi][ni][2 * half + 0];
                float v1 = acc[mi][ni][2 * half + 1];
                const long long gidx = gm * (long long)Nc + gn;
                if (act == 0) {
                    if (bias) { v0 += bias[gn]; v1 += bias[gn + 1]; }
                } else if (act == 1) {
                    v0 = fmaxf(v0 + bias[gn], 0.f);
                    v1 = fmaxf(v1 + bias[gn + 1], 0.f);
                } else {
                    float a0 = aggr[gidx]     + gat_bias[gn];
                    float a1 = aggr[gidx + 1] + gat_bias[gn + 1];
                    a0 = a0 > 0.f ? a0 : (expf(a0) - 1.f);
                    a1 = a1 > 0.f ? a1 : (expf(a1) - 1.f);
                    v0 = a0 + v0 + bias[gn];
                    v1 = a1 + v1 + bias[gn + 1];
                }
                float2 o; o.x = v0; o.y = v1;
                *(float2*)(C + gidx) = o;
            }
        }
    }
}

// ---------------------------------------------------------------------------
// LayerNorm(256) + ReLU in place
// ---------------------------------------------------------------------------
__global__ __launch_bounds__(256)
void ln_relu_kernel(float* __restrict__ x, const float* __restrict__ g,
                    const float* __restrict__ b)
{
    const int row = blockIdx.x;
    float* p = x + (long long)row * 256;
    float v = p[threadIdx.x];
    __shared__ float ws[8];
    const int w = threadIdx.x >> 5, l = threadIdx.x & 31;

    float s = v;
#pragma unroll
    for (int o = 16; o; o >>= 1) s += __shfl_xor_sync(0xffffffffu, s, o);
    if (l == 0) ws[w] = s;
    __syncthreads();
    float m = 0.f;
#pragma unroll
    for (int i = 0; i < 8; i++) m += ws[i];
    m *= (1.f / 256.f);
    __syncthreads();

    float dv = v - m;
    float q = dv * dv;
#pragma unroll
    for (int o = 16; o; o >>= 1) q += __shfl_xor_sync(0xffffffffu, q, o);
    if (l == 0) ws[w] = q;
    __syncthreads();
    float var = 0.f;
#pragma unroll
    for (int i = 0; i < 8; i++) var += ws[i];
    var *= (1.f / 256.f);

    float y = dv * rsqrtf(var + 1e-5f) * g[threadIdx.x] + b[threadIdx.x];
    p[threadIdx.x] = fmaxf(y, 0.f);
}

// ---------------------------------------------------------------------------
// Edge phase (round-2 proven)
// ---------------------------------------------------------------------------
__global__ __launch_bounds__(256)
void att_dots_kernel(const float* __restrict__ hW,
                     const float* __restrict__ att_src,
                     const float* __restrict__ att_dst,
                     float* __restrict__ asrc, float* __restrict__ adst,
                     int N, int H, int C)
{
    long long warp = ((long long)blockIdx.x * blockDim.x + threadIdx.x) >> 5;
    int lane = threadIdx.x & 31;
    if (warp >= (long long)N * H) return;
    int h = (int)(warp % H);
    const float* hp = hW + warp * C;
    const float* as = att_src + h * C;
    const float* ad = att_dst + h * C;
    float s = 0.f, d2 = 0.f;
    for (int c = lane; c < C; c += 32) {
        float hv = hp[c];
        s  += hv * as[c];
        d2 += hv * ad[c];
    }
#pragma unroll
    for (int o = 16; o; o >>= 1) {
        s  += __shfl_down_sync(0xffffffffu, s, o);
        d2 += __shfl_down_sync(0xffffffffu, d2, o);
    }
    if (lane == 0) { asrc[warp] = s; adst[warp] = d2; }
}

__device__ __forceinline__ void atomicMaxF(float* addr, float val)
{
    if (val >= 0.f) atomicMax((int*)addr, __float_as_int(val));
    else            atomicMin((unsigned int*)addr, __float_as_uint(val));
}

__device__ __forceinline__ void edge_ends(const int* __restrict__ srcA,
                                          const int* __restrict__ dstA,
                                          long long e, int E, int& s, int& d)
{
    if (e < E) { s = srcA[e]; d = dstA[e]; }
    else       { s = d = (int)(e - E); }
}

__global__ __launch_bounds__(256)
void edge_logits_kernel(const int* __restrict__ srcA,
                        const int* __restrict__ dstA, int E, int N, int H,
                        const float* __restrict__ asrc,
                        const float* __restrict__ adst,
                        float* __restrict__ ebuf, float* __restrict__ emax)
{
    long long i = (long long)blockIdx.x * blockDim.x + threadIdx.x;
    long long tot = (long long)(E + N) * H;
    if (i >= tot) return;
    long long e = i / H; int h = (int)(i % H);
    int s, d; edge_ends(srcA, dstA, e, E, s, d);
    float v = asrc[(long long)s * H + h] + adst[(long long)d * H + h];
    v = v > 0.f ? v : 0.2f * v;
    ebuf[i] = v;
    atomicMaxF(&emax[(long long)d * H + h], v);
}

__global__ __launch_bounds__(256)
void edge_exp_kernel(const int* __restrict__ srcA,
                     const int* __restrict__ dstA, int E, int N, int H,
                     float* __restrict__ ebuf, const float* __restrict__ emax,
                     float* __restrict__ den)
{
    long long i = (long long)blockIdx.x * blockDim.x + threadIdx.x;
    long long tot = (long long)(E + N) * H;
    if (i >= tot) return;
    long long e = i / H; int h = (int)(i % H);
    int s, d; edge_ends(srcA, dstA, e, E, s, d);
    float ee = expf(ebuf[i] - emax[(long long)d * H + h]);
    ebuf[i] = ee;
    atomicAdd(&den[(long long)d * H + h], ee);
}

__device__ __forceinline__ void redAddV4(float* addr, float4 v)
{
    asm volatile("red.global.add.v4.f32 [%0], {%1, %2, %3, %4};"
                 :: "l"(addr), "f"(v.x), "f"(v.y), "f"(v.z), "f"(v.w)
                 : "memory");
}

__global__ __launch_bounds__(256)
void edge_aggr_kernel(const int* __restrict__ srcA,
                      const int* __restrict__ dstA, int E, int N, int H, int C,
                      const float* __restrict__ ebuf,
                      const float* __restrict__ den,
                      const float* __restrict__ hW, float* __restrict__ out)
{
    long long warp = ((long long)blockIdx.x * blockDim.x + threadIdx.x) >> 5;
    int lane = threadIdx.x & 31;
    long long tot = (long long)(E + N) * H;
    if (warp >= tot) return;
    long long e = warp / H; int h = (int)(warp % H);
    int s, d; edge_ends(srcA, dstA, e, E, s, d);
    float alpha = ebuf[warp] / (den[(long long)d * H + h] + 1e-16f);
    const float4* hp = (const float4*)(hW  + ((long long)s * H + h) * C);
    float*        op = out + ((long long)d * H + h) * C;
    int C4 = C >> 2;
    for (int c = lane; c < C4; c += 32) {
        float4 v = hp[c];
        v.x *= alpha; v.y *= alpha; v.z *= alpha; v.w *= alpha;
        redAddV4(op + c * 4, v);
    }
}

__global__ void fill_kernel(float* __restrict__ p, long long n, float v)
{
    long long i = (long long)blockIdx.x * blockDim.x + threadIdx.x;
    if (i < n) p[i] = v;
}

__global__ void mlp2_kernel(const float* __restrict__ J, const float* __restrict__ w,
                            const float* __restrict__ b, float* __restrict__ out, int N)
{
    int n = blockIdx.x * blockDim.x + threadIdx.x;
    if (n >= N) return;
    const float* r = J + (long long)n * 64;
    float s0 = b[0], s1 = b[1];
#pragma unroll
    for (int k = 0; k < 64; k++) {
        float v = r[k];
        s0 += v * w[k * 2 + 0];
        s1 += v * w[k * 2 + 1];
    }
    out[(long long)n * 2 + 0] = s0;
    out[(long long)n * 2 + 1] = s1;
}

// ---------------------------------------------------------------------------
// Host orchestration
// ---------------------------------------------------------------------------
static inline int kpad64(int k) { return (k + 63) & ~63; }

static inline void run_split_a(const float* X, __nv_bfloat16* Hi, __nv_bfloat16* Lo,
                               int M, int K, int Kp)
{
    long long tot = (long long)M * (Kp >> 2);
    split_a_kernel<<<(unsigned)((tot + 255) / 256), 256>>>(X, Hi, Lo, M, K, Kp);
}
static inline void run_split_bt(const float* B, __nv_bfloat16* Hi, __nv_bfloat16* Lo,
                                int K, int Nc, int Kp)
{
    long long tot = (long long)Nc * (Kp >> 2);
    split_bt_kernel<<<(unsigned)((tot + 255) / 256), 256>>>(B, Hi, Lo, K, Nc, Kp);
}
static inline void run_tc_gemm(const __nv_bfloat16* Ahi, const __nv_bfloat16* Alo,
                               const __nv_bfloat16* Bhi, const __nv_bfloat16* Blo,
                               float* C, int M, int Nc, int Kp,
                               const float* bias, int act,
                               const float* aggr = nullptr,
                               const float* gat_bias = nullptr)
{
    dim3 grid((Nc + 127) / 128, (M + 127) / 128);
    mma_gemm_kernel<<<grid, 256, TC_SMEM>>>(Ahi, Alo, Bhi, Blo, C, M, Nc, Kp,
                                            bias, act, aggr, gat_bias);
}
static inline void run_fill(float* p, long long n, float v)
{
    fill_kernel<<<(unsigned)((n + 255) / 256), 256>>>(p, n, v);
}

static void run_gat_edges(const int* srcA, const int* dstA,
                          int E, int N, int H, int C,
                          const float* hW, const float* att_src, const float* att_dst,
                          float* asrc, float* adst, float* emax, float* den,
                          float* ebuf, float* out)
{
    {
        long long warps = (long long)N * H;
        long long blocks = (warps * 32 + 255) / 256;
        att_dots_kernel<<<(unsigned)blocks, 256>>>(hW, att_src, att_dst, asrc, adst, N, H, C);
    }
    run_fill(emax, (long long)N * H, -INFINITY);
    run_fill(den,  (long long)N * H, 0.f);
    run_fill(out,  (long long)N * H * C, 0.f);

    long long tot = (long long)(E + N) * H;
    {
        long long blocks = (tot + 255) / 256;
        edge_logits_kernel<<<(unsigned)blocks, 256>>>(srcA, dstA, E, N, H, asrc, adst, ebuf, emax);
        edge_exp_kernel<<<(unsigned)blocks, 256>>>(srcA, dstA, E, N, H, ebuf, emax, den);
    }
    {
        long long blocks = (tot * 32 + 255) / 256;
        edge_aggr_kernel<<<(unsigned)blocks, 256>>>(srcA, dstA, E, N, H, C, ebuf, den, hW, out);
    }
}

extern "C" void kernel_launch(void* const* d_in, const int* in_sizes, int n_in,
                              void* d_out, int out_size)
{
    const float* x      = (const float*)d_in[0];
    const int*   ei     = (const int*)d_in[1];
    const float* enc_w1 = (const float*)d_in[2];
    const float* enc_b1 = (const float*)d_in[3];
    const float* ln1_g  = (const float*)d_in[4];
    const float* ln1_b  = (const float*)d_in[5];
    const float* enc_w2 = (const float*)d_in[6];
    const float* enc_b2 = (const float*)d_in[7];
    const float* ln2_g  = (const float*)d_in[8];
    const float* ln2_b  = (const float*)d_in[9];
    const float* w1       = (const float*)d_in[10];
    const float* att_src1 = (const float*)d_in[11];
    const float* att_dst1 = (const float*)d_in[12];
    const float* bias1    = (const float*)d_in[13];
    const float* res1_w   = (const float*)d_in[14];
    const float* res1_b   = (const float*)d_in[15];
    const float* w2       = (const float*)d_in[16];
    const float* att_src2 = (const float*)d_in[17];
    const float* att_dst2 = (const float*)d_in[18];
    const float* bias2    = (const float*)d_in[19];
    const float* res2_w   = (const float*)d_in[20];
    const float* res2_b   = (const float*)d_in[21];
    const float* w3       = (const float*)d_in[22];
    const float* att_src3 = (const float*)d_in[23];
    const float* att_dst3 = (const float*)d_in[24];
    const float* bias3    = (const float*)d_in[25];
    const float* res3_w   = (const float*)d_in[26];
    const float* res3_b   = (const float*)d_in[27];
    const float* mlp_w1   = (const float*)d_in[28];
    const float* mlp_b1   = (const float*)d_in[29];
    const float* mlp_w2   = (const float*)d_in[30];
    const float* mlp_b2   = (const float*)d_in[31];

    const int N = in_sizes[0] / GDIM;
    const int E = in_sizes[1] / 2;
    const int* srcA = ei;
    const int* dstA = ei + E;

    cudaFuncSetAttribute(mma_gemm_kernel,
                         cudaFuncAttributeMaxDynamicSharedMemorySize, TC_SMEM);

    float *t1, *henc, *A, *B, *D, *E2, *G, *Hh, *J;
    float *asrc, *adst, *emax, *den, *ebuf;
    __nv_bfloat16 *sAhi, *sAlo, *sBhi, *sBlo;
    cudaGetSymbolAddress((void**)&t1,   g_t1);
    cudaGetSymbolAddress((void**)&henc, g_henc);
    cudaGetSymbolAddress((void**)&A,    g_A);
    cudaGetSymbolAddress((void**)&B,    g_B);
    cudaGetSymbolAddress((void**)&D,    g_D);
    cudaGetSymbolAddress((void**)&E2,   g_E2);
    cudaGetSymbolAddress((void**)&G,    g_G);
    cudaGetSymbolAddress((void**)&Hh,   g_Hh);
    cudaGetSymbolAddress((void**)&J,    g_J);
    cudaGetSymbolAddress((void**)&asrc, g_asrc);
    cudaGetSymbolAddress((void**)&adst, g_adst);
    cudaGetSymbolAddress((void**)&emax, g_emax);
    cudaGetSymbolAddress((void**)&den,  g_den);
    cudaGetSymbolAddress((void**)&ebuf, g_ebuf);
    cudaGetSymbolAddress((void**)&sAhi, g_sAhi);
    cudaGetSymbolAddress((void**)&sAlo, g_sAlo);
    cudaGetSymbolAddress((void**)&sBhi, g_sBhi);
    cudaGetSymbolAddress((void**)&sBlo, g_sBlo);

    // ---- JointEncoder ----
    {
        int Kp = kpad64(GDIM);   // 448
        run_split_a(x, sAhi, sAlo, N, GDIM, Kp);
        run_split_bt(enc_w1, sBhi, sBlo, GDIM, 256, Kp);
        run_tc_gemm(sAhi, sAlo, sBhi, sBlo, t1, N, 256, Kp, enc_b1, 0);
        ln_relu_kernel<<<N, 256>>>(t1, ln1_g, ln1_b);

        run_split_a(t1, sAhi, sAlo, N, 256, 256);
        run_split_bt(enc_w2, sBhi, sBlo, 256, 256, 256);
        run_tc_gemm(sAhi, sAlo, sBhi, sBlo, henc, N, 256, 256, enc_b2, 0);
        ln_relu_kernel<<<N, 256>>>(henc, ln2_g, ln2_b);
    }

    // ---- Block 1: GAT 256 -> 4x256 (concat) ----
    {
        run_split_a(henc, sAhi, sAlo, N, 256, 256);
        run_split_bt(w1, sBhi, sBlo, 256, 1024, 256);
        run_tc_gemm(sAhi, sAlo, sBhi, sBlo, A, N, 1024, 256, nullptr, 0);      // hW1
        run_gat_edges(srcA, dstA, E, N, 4, 256, A, att_src1, att_dst1,
                      asrc, adst, emax, den, ebuf, B);                          // aggr1
        run_split_bt(res1_w, sBhi, sBlo, 256, 1024, 256);
        run_tc_gemm(sAhi, sAlo, sBhi, sBlo, A, N, 1024, 256, res1_b, 2, B, bias1); // h1
    }

    // ---- Block 2: GAT 1024 -> 2x96 (concat) ----
    {
        run_split_a(A, sAhi, sAlo, N, 1024, 1024);
        run_split_bt(w2, sBhi, sBlo, 1024, 192, 1024);
        run_tc_gemm(sAhi, sAlo, sBhi, sBlo, D, N, 192, 1024, nullptr, 0);      // hW2
        run_gat_edges(srcA, dstA, E, N, 2, 96, D, att_src2, att_dst2,
                      asrc, adst, emax, den, ebuf, E2);                         // aggr2
        run_split_bt(res2_w, sBhi, sBlo, 1024, 192, 1024);
        run_tc_gemm(sAhi, sAlo, sBhi, sBlo, D, N, 192, 1024, res2_b, 2, E2, bias2); // h2
    }

    // ---- Block 3: GAT 192 -> 1x128 (no concat, 1 head) ----
    {
        run_split_a(D, sAhi, sAlo, N, 192, 192);
        run_split_bt(w3, sBhi, sBlo, 192, 128, 192);
        run_tc_gemm(sAhi, sAlo, sBhi, sBlo, G, N, 128, 192, nullptr, 0);       // hW3
        run_gat_edges(srcA, dstA, E, N, 1, 128, G, att_src3, att_dst3,
                      asrc, adst, emax, den, ebuf, Hh);                         // aggr3
        run_split_bt(res3_w, sBhi, sBlo, 192, 128, 192);
        run_tc_gemm(sAhi, sAlo, sBhi, sBlo, G, N, 128, 192, res3_b, 2, Hh, bias3); // h3
    }

    // ---- MLP head ----
    {
        run_split_a(G, sAhi, sAlo, N, 128, 128);
        run_split_bt(mlp_w1, sBhi, sBlo, 128, 64, 128);
        run_tc_gemm(sAhi, sAlo, sBhi, sBlo, J, N, 64, 128, mlp_b1, 1);
        mlp2_kernel<<<(N + 255) / 256, 256>>>(J, mlp_w2, mlp_b2, (float*)d_out, N);
    }
}

// round 5
// speedup vs baseline: 2.8769x; 1.2727x over previous
#include <cuda_runtime.h>
#include <cuda_bf16.h>
#include <math.h>

// ---------------------------------------------------------------------------
// Problem constants
// ---------------------------------------------------------------------------
#define NMAX 50000
#define EDGEMAX 300000
#define ETOT (EDGEMAX + NMAX)
#define GDIM 405
#define NB_SCAN 49   // ceil(50000/1024)

// ---------------------------------------------------------------------------
// Device scratch
// ---------------------------------------------------------------------------
__device__ float g_t1  [NMAX * 256];
__device__ float g_henc[NMAX * 256];
__device__ float g_A   [NMAX * 1024];   // hW1
__device__ float g_B   [NMAX * 1024];   // aggr1
__device__ float g_D   [NMAX * 192];    // hW2
__device__ float g_E2  [NMAX * 192];    // aggr2
__device__ float g_G   [NMAX * 128];    // hW3
__device__ float g_Hh  [NMAX * 128];    // aggr3
__device__ float g_J   [NMAX * 64];
__device__ float g_asrc[NMAX * 4];
__device__ float g_adst[NMAX * 4];
// CSR
__device__ int g_deg[NMAX];
__device__ int g_off[NMAX + 1];
__device__ int g_pos[NMAX];
__device__ int g_csr[ETOT];
__device__ int g_blk[64];
// bf16 split buffers (ping-pong A pairs + weight pair)
__device__ __nv_bfloat16 g_b1hi[NMAX * 1024];
__device__ __nv_bfloat16 g_b1lo[NMAX * 1024];
__device__ __nv_bfloat16 g_b2hi[NMAX * 1024];
__device__ __nv_bfloat16 g_b2lo[NMAX * 1024];
__device__ __nv_bfloat16 g_whi[1024 * 1024];
__device__ __nv_bfloat16 g_wlo[1024 * 1024];

// ---------------------------------------------------------------------------
// Baseline-PTX helpers
// ---------------------------------------------------------------------------
__device__ __forceinline__ unsigned smem_u32(const void* p) {
    unsigned a;
    asm("{ .reg .u64 t; cvta.to.shared.u64 t, %1; cvt.u32.u64 %0, t; }"
        : "=r"(a) : "l"(p));
    return a;
}
__device__ __forceinline__ void cp16(unsigned d, const void* s, unsigned srcsz) {
    asm volatile("cp.async.cg.shared.global [%0], [%1], 16, %2;"
                 :: "r"(d), "l"(s), "r"(srcsz) : "memory");
}
__device__ __forceinline__ void cp_commit() {
    asm volatile("cp.async.commit_group;" ::: "memory");
}
__device__ __forceinline__ void ldsm4(unsigned r[4], unsigned addr) {
    asm volatile("ldmatrix.sync.aligned.m8n8.x4.shared.b16 {%0,%1,%2,%3}, [%4];"
                 : "=r"(r[0]), "=r"(r[1]), "=r"(r[2]), "=r"(r[3]) : "r"(addr));
}
__device__ __forceinline__ void mma16816(float c[4], const unsigned a[4],
                                         const unsigned b0, const unsigned b1) {
    asm volatile(
        "mma.sync.aligned.m16n8k16.row.col.f32.bf16.bf16.f32 "
        "{%0,%1,%2,%3}, {%4,%5,%6,%7}, {%8,%9}, {%0,%1,%2,%3};"
        : "+f"(c[0]), "+f"(c[1]), "+f"(c[2]), "+f"(c[3])
        : "r"(a[0]), "r"(a[1]), "r"(a[2]), "r"(a[3]), "r"(b0), "r"(b1));
}

__device__ __forceinline__ void split2(float v0, float v1,
                                       __nv_bfloat16* Hi, __nv_bfloat16* Lo,
                                       long long idx) {
    __nv_bfloat16 h0 = __float2bfloat16(v0);
    __nv_bfloat16 h1 = __float2bfloat16(v1);
    __nv_bfloat16 l0 = __float2bfloat16(v0 - __bfloat162float(h0));
    __nv_bfloat16 l1 = __float2bfloat16(v1 - __bfloat162float(h1));
    ushort2 uh; uh.x = __bfloat16_as_ushort(h0); uh.y = __bfloat16_as_ushort(h1);
    ushort2 ul; ul.x = __bfloat16_as_ushort(l0); ul.y = __bfloat16_as_ushort(l1);
    *(ushort2*)(Hi + idx) = uh;
    *(ushort2*)(Lo + idx) = ul;
}

// ---------------------------------------------------------------------------
// Split kernels (input x and weights only)
// ---------------------------------------------------------------------------
__device__ __forceinline__ void split4(const float v[4],
                                       unsigned long long& hp, unsigned long long& lp) {
    unsigned long long h = 0, l = 0;
#pragma unroll
    for (int j = 0; j < 4; j++) {
        __nv_bfloat16 hb = __float2bfloat16(v[j]);
        __nv_bfloat16 lb = __float2bfloat16(v[j] - __bfloat162float(hb));
        h |= (unsigned long long)__bfloat16_as_ushort(hb) << (16 * j);
        l |= (unsigned long long)__bfloat16_as_ushort(lb) << (16 * j);
    }
    hp = h; lp = l;
}

__global__ void split_a_kernel(const float* __restrict__ X,
                               __nv_bfloat16* __restrict__ Hi,
                               __nv_bfloat16* __restrict__ Lo,
                               int M, int K, int Kpad)
{
    long long i = (long long)blockIdx.x * blockDim.x + threadIdx.x;
    long long tot = (long long)M * (Kpad >> 2);
    if (i >= tot) return;
    int k4 = (int)(i % (Kpad >> 2));
    long long row = i / (Kpad >> 2);
    float v[4];
#pragma unroll
    for (int j = 0; j < 4; j++) {
        int kk = 4 * k4 + j;
        v[j] = (kk < K) ? X[row * K + kk] : 0.f;
    }
    unsigned long long hp, lp;
    split4(v, hp, lp);
    *(unsigned long long*)(Hi + row * Kpad + 4 * k4) = hp;
    *(unsigned long long*)(Lo + row * Kpad + 4 * k4) = lp;
}

__global__ void split_bt_kernel(const float* __restrict__ B,
                                __nv_bfloat16* __restrict__ Hi,
                                __nv_bfloat16* __restrict__ Lo,
                                int K, int Nc, int Kpad)
{
    long long i = (long long)blockIdx.x * blockDim.x + threadIdx.x;
    long long tot = (long long)Nc * (Kpad >> 2);
    if (i >= tot) return;
    int n  = (int)(i % Nc);
    int k4 = (int)(i / Nc);
    float v[4];
#pragma unroll
    for (int j = 0; j < 4; j++) {
        int kk = 4 * k4 + j;
        v[j] = (kk < K) ? B[(long long)kk * Nc + n] : 0.f;
    }
    unsigned long long hp, lp;
    split4(v, hp, lp);
    *(unsigned long long*)(Hi + (long long)n * Kpad + 4 * k4) = hp;
    *(unsigned long long*)(Lo + (long long)n * Kpad + 4 * k4) = lp;
}

// ---------------------------------------------------------------------------
// Tensor-core GEMM (3-term bf16 split). Epilogue optionally writes:
//   Cf   : fp32 result        (nullable)
//   Chi/Clo : bf16 split of result (nullable) — feeds next GEMM's A
// act: 0 = (+bias), 1 = relu(+bias), 2 = elu(aggr+gat_bias) + acc + bias
// ---------------------------------------------------------------------------
#define ROWB 80
#define MATB (128 * ROWB)
#define OFF_AH 0
#define OFF_AL (1 * MATB)
#define OFF_BH (2 * MATB)
#define OFF_BL (3 * MATB)
#define BUFB (4 * MATB)
#define TC_SMEM (2 * BUFB)

__global__ __launch_bounds__(256)
void mma_gemm_kernel(const __nv_bfloat16* __restrict__ Ahi,
                     const __nv_bfloat16* __restrict__ Alo,
                     const __nv_bfloat16* __restrict__ Bhi,
                     const __nv_bfloat16* __restrict__ Blo,
                     float* __restrict__ Cf,
                     __nv_bfloat16* __restrict__ Chi,
                     __nv_bfloat16* __restrict__ Clo,
                     int M, int Nc, int Kpad,
                     const float* __restrict__ bias, int act,
                     const float* __restrict__ aggr,
                     const float* __restrict__ gat_bias)
{
    extern __shared__ char smem[];
    const unsigned sb = smem_u32(smem);
    const int tid = threadIdx.x;
    const int wid = tid >> 5, lane = tid & 31;
    const int bm = blockIdx.y * 128;
    const int bn = blockIdx.x * 128;
    const int Ntile = min(128, Nc - bn);
    const int warp_m = wid & 3;
    const int warp_n = wid >> 2;
    const int NCH = Kpad >> 5;

    float acc[2][8][4];
#pragma unroll
    for (int mi = 0; mi < 2; mi++)
#pragma unroll
        for (int ni = 0; ni < 8; ni++)
#pragma unroll
            for (int q = 0; q < 4; q++) acc[mi][ni][q] = 0.f;

    const int lrow = tid >> 1;
    const int lc0  = (tid & 1) * 2;

    const long long gmA = bm + lrow;
    const unsigned okA = (gmA < M) ? 16u : 0u;
    const long long rowA = (okA ? gmA : 0) * (long long)Kpad;
    const unsigned okB = (lrow < Ntile) ? 16u : 0u;
    const long long rowB = (long long)(okB ? (bn + lrow) : 0) * Kpad;

#define LOAD_CHUNK(c)                                                          \
    do {                                                                       \
        const unsigned bd = sb + ((c) & 1) * BUFB;                             \
        const long long kb = (long long)(c) * 32;                              \
        _Pragma("unroll")                                                      \
        for (int j = 0; j < 2; j++) {                                          \
            const int ch = lc0 + j;                                            \
            const unsigned so = lrow * ROWB + ch * 16;                         \
            const long long go = kb + ch * 8;                                  \
            cp16(bd + OFF_AH + so, Ahi + rowA + go, okA);                      \
            cp16(bd + OFF_AL + so, Alo + rowA + go, okA);                      \
            cp16(bd + OFF_BH + so, Bhi + rowB + go, okB);                      \
            cp16(bd + OFF_BL + so, Blo + rowB + go, okB);                      \
        }                                                                      \
    } while (0)

    LOAD_CHUNK(0);
    cp_commit();

    for (int c = 0; c < NCH; c++) {
        if (c + 1 < NCH) {
            LOAD_CHUNK(c + 1);
            cp_commit();
            asm volatile("cp.async.wait_group 1;" ::: "memory");
        } else {
            asm volatile("cp.async.wait_group 0;" ::: "memory");
        }
        __syncthreads();

        const unsigned bd = sb + (c & 1) * BUFB;
#pragma unroll
        for (int ks = 0; ks < 2; ks++) {
            unsigned ah[2][4], al[2][4];
#pragma unroll
            for (int mi = 0; mi < 2; mi++) {
                const int row = warp_m * 32 + mi * 16 + (lane & 15);
                const int ch  = ks * 2 + (lane >> 4);
                const unsigned off = row * ROWB + ch * 16;
                ldsm4(ah[mi], bd + OFF_AH + off);
                ldsm4(al[mi], bd + OFF_AL + off);
            }
            unsigned bh[8][2], bl[8][2];
#pragma unroll
            for (int np = 0; np < 4; np++) {
                const int row = warp_n * 64 + np * 16 + ((lane >> 4) & 1) * 8 + (lane & 7);
                const int ch  = ks * 2 + ((lane >> 3) & 1);
                const unsigned off = row * ROWB + ch * 16;
                unsigned r[4];
                ldsm4(r, bd + OFF_BH + off);
                bh[2 * np][0] = r[0]; bh[2 * np][1] = r[1];
                bh[2 * np + 1][0] = r[2]; bh[2 * np + 1][1] = r[3];
                ldsm4(r, bd + OFF_BL + off);
                bl[2 * np][0] = r[0]; bl[2 * np][1] = r[1];
                bl[2 * np + 1][0] = r[2]; bl[2 * np + 1][1] = r[3];
            }
#pragma unroll
            for (int mi = 0; mi < 2; mi++)
#pragma unroll
                for (int ni = 0; ni < 8; ni++) {
                    mma16816(acc[mi][ni], ah[mi], bh[ni][0], bh[ni][1]);
                    mma16816(acc[mi][ni], ah[mi], bl[ni][0], bl[ni][1]);
                    mma16816(acc[mi][ni], al[mi], bh[ni][0], bh[ni][1]);
                }
        }
        __syncthreads();
    }

    // epilogue
#pragma unroll
    for (int mi = 0; mi < 2; mi++) {
#pragma unroll
        for (int half = 0; half < 2; half++) {
            const long long gm = bm + warp_m * 32 + mi * 16 + (lane >> 2) + half * 8;
            if (gm >= M) continue;
#pragma unroll
            for (int ni = 0; ni < 8; ni++) {
                const int gn = bn + warp_n * 64 + ni * 8 + (lane & 3) * 2;
                if (gn >= Nc) continue;
                float v0 = acc[mi][ni][2 * half + 0];
                float v1 = acc[mi][ni][2 * half + 1];
                const long long gidx = gm * (long long)Nc + gn;
                if (act == 0) {
                    if (bias) { v0 += bias[gn]; v1 += bias[gn + 1]; }
                } else if (act == 1) {
                    v0 = fmaxf(v0 + bias[gn], 0.f);
                    v1 = fmaxf(v1 + bias[gn + 1], 0.f);
                } else {
                    float a0 = aggr[gidx]     + gat_bias[gn];
                    float a1 = aggr[gidx + 1] + gat_bias[gn + 1];
                    a0 = a0 > 0.f ? a0 : (expf(a0) - 1.f);
                    a1 = a1 > 0.f ? a1 : (expf(a1) - 1.f);
                    v0 = a0 + v0 + bias[gn];
                    v1 = a1 + v1 + bias[gn + 1];
                }
                if (Cf) { float2 o; o.x = v0; o.y = v1; *(float2*)(Cf + gidx) = o; }
                if (Chi) split2(v0, v1, Chi, Clo, gidx);
            }
        }
    }
}

// ---------------------------------------------------------------------------
// LayerNorm(256) + ReLU; emits bf16 hi/lo split (no fp32 store needed)
// ---------------------------------------------------------------------------
__global__ __launch_bounds__(256)
void ln_relu_kernel(const float* __restrict__ x, const float* __restrict__ g,
                    const float* __restrict__ b,
                    __nv_bfloat16* __restrict__ Hi,
                    __nv_bfloat16* __restrict__ Lo)
{
    const int row = blockIdx.x;
    const float* p = x + (long long)row * 256;
    float v = p[threadIdx.x];
    __shared__ float ws[8];
    const int w = threadIdx.x >> 5, l = threadIdx.x & 31;

    float s = v;
#pragma unroll
    for (int o = 16; o; o >>= 1) s += __shfl_xor_sync(0xffffffffu, s, o);
    if (l == 0) ws[w] = s;
    __syncthreads();
    float m = 0.f;
#pragma unroll
    for (int i = 0; i < 8; i++) m += ws[i];
    m *= (1.f / 256.f);
    __syncthreads();

    float dv = v - m;
    float q = dv * dv;
#pragma unroll
    for (int o = 16; o; o >>= 1) q += __shfl_xor_sync(0xffffffffu, q, o);
    if (l == 0) ws[w] = q;
    __syncthreads();
    float var = 0.f;
#pragma unroll
    for (int i = 0; i < 8; i++) var += ws[i];
    var *= (1.f / 256.f);

    float y = dv * rsqrtf(var + 1e-5f) * g[threadIdx.x] + b[threadIdx.x];
    y = fmaxf(y, 0.f);

    long long idx = (long long)row * 256 + threadIdx.x;
    __nv_bfloat16 hb = __float2bfloat16(y);
    __nv_bfloat16 lb = __float2bfloat16(y - __bfloat162float(hb));
    Hi[idx] = hb; Lo[idx] = lb;
}

// ---------------------------------------------------------------------------
// CSR build (edge list constant across the 3 GAT layers)
// ---------------------------------------------------------------------------
__global__ void deg_init_kernel(int* deg, int N)
{
    int i = blockIdx.x * blockDim.x + threadIdx.x;
    if (i < N) deg[i] = 1;    // self loop
}
__global__ void deg_hist_kernel(const int* __restrict__ dst, int E, int* deg)
{
    int i = blockIdx.x * blockDim.x + threadIdx.x;
    if (i < E) atomicAdd(&deg[dst[i]], 1);
}
__global__ __launch_bounds__(1024)
void scan1_kernel(const int* __restrict__ deg, int* __restrict__ off,
                  int* __restrict__ blk, int N)
{
    __shared__ int sh[1024];
    int t = threadIdx.x;
    int i = blockIdx.x * 1024 + t;
    sh[t] = (i < N) ? deg[i] : 0;
    __syncthreads();
    for (int o = 1; o < 1024; o <<= 1) {
        int x = (t >= o) ? sh[t - o] : 0;
        __syncthreads();
        sh[t] += x;
        __syncthreads();
    }
    if (i < N) off[i + 1] = sh[t];
    if (t == 1023) blk[blockIdx.x] = sh[1023];
}
__global__ __launch_bounds__(64)
void scan2_kernel(int* blk, int nb)   // single block; inclusive in place
{
    __shared__ int sh[64];
    int t = threadIdx.x;
    sh[t] = (t < nb) ? blk[t] : 0;
    __syncthreads();
    for (int o = 1; o < 64; o <<= 1) {
        int x = (t >= o) ? sh[t - o] : 0;
        __syncthreads();
        sh[t] += x;
        __syncthreads();
    }
    if (t < nb) blk[t] = sh[t];
}
__global__ void scan3_kernel(int* off, const int* __restrict__ blk, int N)
{
    int i = blockIdx.x * blockDim.x + threadIdx.x;
    if (i == 0) off[0] = 0;
    if (i < N) {
        int b = i >> 10;
        if (b > 0) off[i + 1] += blk[b - 1];
    }
}
__global__ void pos_init_kernel(const int* __restrict__ off, int* pos,
                                int* csr, int N)
{
    int i = blockIdx.x * blockDim.x + threadIdx.x;
    if (i < N) {
        int o = off[i];
        pos[i] = o + 1;
        csr[o] = i;          // self loop at slot 0
    }
}
__global__ void scatter_kernel(const int* __restrict__ src,
                               const int* __restrict__ dst, int E,
                               int* pos, int* csr)
{
    int i = blockIdx.x * blockDim.x + threadIdx.x;
    if (i < E) {
        int p = atomicAdd(&pos[dst[i]], 1);
        csr[p] = src[i];
    }
}

// ---------------------------------------------------------------------------
// Attention dot products (unchanged)
// ---------------------------------------------------------------------------
__global__ __launch_bounds__(256)
void att_dots_kernel(const float* __restrict__ hW,
                     const float* __restrict__ att_src,
                     const float* __restrict__ att_dst,
                     float* __restrict__ asrc, float* __restrict__ adst,
                     int N, int H, int C)
{
    long long warp = ((long long)blockIdx.x * blockDim.x + threadIdx.x) >> 5;
    int lane = threadIdx.x & 31;
    if (warp >= (long long)N * H) return;
    int h = (int)(warp % H);
    const float* hp = hW + warp * C;
    const float* as = att_src + h * C;
    const float* ad = att_dst + h * C;
    float s = 0.f, d2 = 0.f;
    for (int c = lane; c < C; c += 32) {
        float hv = hp[c];
        s  += hv * as[c];
        d2 += hv * ad[c];
    }
#pragma unroll
    for (int o = 16; o; o >>= 1) {
        s  += __shfl_down_sync(0xffffffffu, s, o);
        d2 += __shfl_down_sync(0xffffffffu, d2, o);
    }
    if (lane == 0) { asrc[warp] = s; adst[warp] = d2; }
}

// ---------------------------------------------------------------------------
// Fused GAT softmax-aggregate: one warp per (dst node, head), CSR neighbors.
// pass1: max logit; pass2: accumulate Σee·h[src] and Σee; divide once.
// ---------------------------------------------------------------------------
__global__ __launch_bounds__(256)
void gat_aggr_csr_kernel(const int* __restrict__ off,
                         const int* __restrict__ csr,
                         const float* __restrict__ asrc,
                         const float* __restrict__ adst,
                         const float* __restrict__ hW,
                         float* __restrict__ out,
                         int N, int H, int C)
{
    long long warp = ((long long)blockIdx.x * blockDim.x + threadIdx.x) >> 5;
    const int lane = threadIdx.x & 31;
    if (warp >= (long long)N * H) return;
    const int n = (int)(warp / H);
    const int h = (int)(warp % H);
    const int beg = off[n], deg = off[n + 1] - beg;
    const float adv = adst[(long long)n * H + h];
    const int C4 = C >> 2;

    // pass 1: max
    float mx = -INFINITY;
    for (int i = lane; i < deg; i += 32) {
        int s = csr[beg + i];
        float e = asrc[(long long)s * H + h] + adv;
        e = e > 0.f ? e : 0.2f * e;
        mx = fmaxf(mx, e);
    }
#pragma unroll
    for (int o = 16; o; o >>= 1)
        mx = fmaxf(mx, __shfl_xor_sync(0xffffffffu, mx, o));

    // pass 2: accumulate
    float den = 0.f;
    float4 a0 = make_float4(0.f, 0.f, 0.f, 0.f);
    float4 a1 = make_float4(0.f, 0.f, 0.f, 0.f);
    const bool g0 = lane < C4;
    const bool g1 = 32 + lane < C4;
    for (int i = 0; i < deg; i++) {
        int s = csr[beg + i];
        float e = asrc[(long long)s * H + h] + adv;
        e = e > 0.f ? e : 0.2f * e;
        float ee = expf(e - mx);
        den += ee;
        const float4* hp = (const float4*)(hW + ((long long)s * H + h) * C);
        if (g0) {
            float4 f = hp[lane];
            a0.x += ee * f.x; a0.y += ee * f.y; a0.z += ee * f.z; a0.w += ee * f.w;
        }
        if (g1) {
            float4 f = hp[32 + lane];
            a1.x += ee * f.x; a1.y += ee * f.y; a1.z += ee * f.z; a1.w += ee * f.w;
        }
    }
    float inv = 1.f / (den + 1e-16f);
    float4* op = (float4*)(out + ((long long)n * H + h) * C);
    if (g0) {
        a0.x *= inv; a0.y *= inv; a0.z *= inv; a0.w *= inv;
        op[lane] = a0;
    }
    if (g1) {
        a1.x *= inv; a1.y *= inv; a1.z *= inv; a1.w *= inv;
        op[32 + lane] = a1;
    }
}

// ---------------------------------------------------------------------------
// Final 64->2 head
// ---------------------------------------------------------------------------
__global__ void mlp2_kernel(const float* __restrict__ J, const float* __restrict__ w,
                            const float* __restrict__ b, float* __restrict__ out, int N)
{
    int n = blockIdx.x * blockDim.x + threadIdx.x;
    if (n >= N) return;
    const float* r = J + (long long)n * 64;
    float s0 = b[0], s1 = b[1];
#pragma unroll
    for (int k = 0; k < 64; k++) {
        float v = r[k];
        s0 += v * w[k * 2 + 0];
        s1 += v * w[k * 2 + 1];
    }
    out[(long long)n * 2 + 0] = s0;
    out[(long long)n * 2 + 1] = s1;
}

// ---------------------------------------------------------------------------
// Host orchestration
// ---------------------------------------------------------------------------
static inline int kpad64(int k) { return (k + 63) & ~63; }

static inline void run_split_bt(const float* B, __nv_bfloat16* Hi, __nv_bfloat16* Lo,
                                int K, int Nc, int Kp)
{
    long long tot = (long long)Nc * (Kp >> 2);
    split_bt_kernel<<<(unsigned)((tot + 255) / 256), 256>>>(B, Hi, Lo, K, Nc, Kp);
}
static inline void run_gemm(const __nv_bfloat16* Ahi, const __nv_bfloat16* Alo,
                            const __nv_bfloat16* Bhi, const __nv_bfloat16* Blo,
                            float* Cf, __nv_bfloat16* Chi, __nv_bfloat16* Clo,
                            int M, int Nc, int Kp,
                            const float* bias, int act,
                            const float* aggr = nullptr,
                            const float* gat_bias = nullptr)
{
    dim3 grid((Nc + 127) / 128, (M + 127) / 128);
    mma_gemm_kernel<<<grid, 256, TC_SMEM>>>(Ahi, Alo, Bhi, Blo, Cf, Chi, Clo,
                                            M, Nc, Kp, bias, act, aggr, gat_bias);
}

static void run_gat(const int* off, const int* csr, int N, int H, int C,
                    const float* hW, const float* att_src, const float* att_dst,
                    float* asrc, float* adst, float* out)
{
    long long warps = (long long)N * H;
    long long blocks = (warps * 32 + 255) / 256;
    att_dots_kernel<<<(unsigned)blocks, 256>>>(hW, att_src, att_dst, asrc, adst, N, H, C);
    gat_aggr_csr_kernel<<<(unsigned)blocks, 256>>>(off, csr, asrc, adst, hW, out, N, H, C);
}

extern "C" void kernel_launch(void* const* d_in, const int* in_sizes, int n_in,
                              void* d_out, int out_size)
{
    const float* x      = (const float*)d_in[0];
    const int*   ei     = (const int*)d_in[1];
    const float* enc_w1 = (const float*)d_in[2];
    const float* enc_b1 = (const float*)d_in[3];
    const float* ln1_g  = (const float*)d_in[4];
    const float* ln1_b  = (const float*)d_in[5];
    const float* enc_w2 = (const float*)d_in[6];
    const float* enc_b2 = (const float*)d_in[7];
    const float* ln2_g  = (const float*)d_in[8];
    const float* ln2_b  = (const float*)d_in[9];
    const float* w1       = (const float*)d_in[10];
    const float* att_src1 = (const float*)d_in[11];
    const float* att_dst1 = (const float*)d_in[12];
    const float* bias1    = (const float*)d_in[13];
    const float* res1_w   = (const float*)d_in[14];
    const float* res1_b   = (const float*)d_in[15];
    const float* w2       = (const float*)d_in[16];
    const float* att_src2 = (const float*)d_in[17];
    const float* att_dst2 = (const float*)d_in[18];
    const float* bias2    = (const float*)d_in[19];
    const float* res2_w   = (const float*)d_in[20];
    const float* res2_b   = (const float*)d_in[21];
    const float* w3       = (const float*)d_in[22];
    const float* att_src3 = (const float*)d_in[23];
    const float* att_dst3 = (const float*)d_in[24];
    const float* bias3    = (const float*)d_in[25];
    const float* res3_w   = (const float*)d_in[26];
    const float* res3_b   = (const float*)d_in[27];
    const float* mlp_w1   = (const float*)d_in[28];
    const float* mlp_b1   = (const float*)d_in[29];
    const float* mlp_w2   = (const float*)d_in[30];
    const float* mlp_b2   = (const float*)d_in[31];

    const int N = in_sizes[0] / GDIM;
    const int E = in_sizes[1] / 2;
    const int* srcA = ei;
    const int* dstA = ei + E;

    cudaFuncSetAttribute(mma_gemm_kernel,
                         cudaFuncAttributeMaxDynamicSharedMemorySize, TC_SMEM);

    float *t1, *henc, *A, *B, *D, *E2, *G, *Hh, *J, *asrc, *adst;
    int *deg, *off, *pos, *csr, *blk;
    __nv_bfloat16 *b1hi, *b1lo, *b2hi, *b2lo, *whi, *wlo;
    cudaGetSymbolAddress((void**)&t1,   g_t1);
    cudaGetSymbolAddress((void**)&henc, g_henc);
    cudaGetSymbolAddress((void**)&A,    g_A);
    cudaGetSymbolAddress((void**)&B,    g_B);
    cudaGetSymbolAddress((void**)&D,    g_D);
    cudaGetSymbolAddress((void**)&E2,   g_E2);
    cudaGetSymbolAddress((void**)&G,    g_G);
    cudaGetSymbolAddress((void**)&Hh,   g_Hh);
    cudaGetSymbolAddress((void**)&J,    g_J);
    cudaGetSymbolAddress((void**)&asrc, g_asrc);
    cudaGetSymbolAddress((void**)&adst, g_adst);
    cudaGetSymbolAddress((void**)&deg,  g_deg);
    cudaGetSymbolAddress((void**)&off,  g_off);
    cudaGetSymbolAddress((void**)&pos,  g_pos);
    cudaGetSymbolAddress((void**)&csr,  g_csr);
    cudaGetSymbolAddress((void**)&blk,  g_blk);
    cudaGetSymbolAddress((void**)&b1hi, g_b1hi);
    cudaGetSymbolAddress((void**)&b1lo, g_b1lo);
    cudaGetSymbolAddress((void**)&b2hi, g_b2hi);
    cudaGetSymbolAddress((void**)&b2lo, g_b2lo);
    cudaGetSymbolAddress((void**)&whi,  g_whi);
    cudaGetSymbolAddress((void**)&wlo,  g_wlo);

    // ---- CSR build (shared by all 3 GAT layers) ----
    deg_init_kernel<<<(N + 255) / 256, 256>>>(deg, N);
    deg_hist_kernel<<<(E + 255) / 256, 256>>>(dstA, E, deg);
    scan1_kernel<<<NB_SCAN, 1024>>>(deg, off, blk, N);
    scan2_kernel<<<1, 64>>>(blk, NB_SCAN);
    scan3_kernel<<<(N + 255) / 256, 256>>>(off, blk, N);
    pos_init_kernel<<<(N + 255) / 256, 256>>>(off, pos, csr, N);
    scatter_kernel<<<(E + 255) / 256, 256>>>(srcA, dstA, E, pos, csr);

    // ---- JointEncoder ----
    {
        int Kp = kpad64(GDIM);   // 448
        long long tot = (long long)N * (Kp >> 2);
        split_a_kernel<<<(unsigned)((tot + 255) / 256), 256>>>(x, b1hi, b1lo, N, GDIM, Kp);
        run_split_bt(enc_w1, whi, wlo, GDIM, 256, Kp);
        run_gemm(b1hi, b1lo, whi, wlo, t1, nullptr, nullptr, N, 256, Kp, enc_b1, 0);
        ln_relu_kernel<<<N, 256>>>(t1, ln1_g, ln1_b, b2hi, b2lo);

        run_split_bt(enc_w2, whi, wlo, 256, 256, 256);
        run_gemm(b2hi, b2lo, whi, wlo, henc, nullptr, nullptr, N, 256, 256, enc_b2, 0);
        ln_relu_kernel<<<N, 256>>>(henc, ln2_g, ln2_b, b1hi, b1lo);
    }

    // ---- Block 1: GAT 256 -> 4x256 (concat) ----
    {
        run_split_bt(w1, whi, wlo, 256, 1024, 256);
        run_gemm(b1hi, b1lo, whi, wlo, A, nullptr, nullptr, N, 1024, 256, nullptr, 0); // hW1
        run_gat(off, csr, N, 4, 256, A, att_src1, att_dst1, asrc, adst, B);            // aggr1
        run_split_bt(res1_w, whi, wlo, 256, 1024, 256);
        run_gemm(b1hi, b1lo, whi, wlo, nullptr, b2hi, b2lo,
                 N, 1024, 256, res1_b, 2, B, bias1);                                   // h1 -> split
    }

    // ---- Block 2: GAT 1024 -> 2x96 (concat) ----
    {
        run_split_bt(w2, whi, wlo, 1024, 192, 1024);
        run_gemm(b2hi, b2lo, whi, wlo, D, nullptr, nullptr, N, 192, 1024, nullptr, 0); // hW2
        run_gat(off, csr, N, 2, 96, D, att_src2, att_dst2, asrc, adst, E2);            // aggr2
        run_split_bt(res2_w, whi, wlo, 1024, 192, 1024);
        run_gemm(b2hi, b2lo, whi, wlo, nullptr, b1hi, b1lo,
                 N, 192, 1024, res2_b, 2, E2, bias2);                                  // h2 -> split
    }

    // ---- Block 3: GAT 192 -> 1x128 (no concat) ----
    {
        run_split_bt(w3, whi, wlo, 192, 128, 192);
        run_gemm(b1hi, b1lo, whi, wlo, G, nullptr, nullptr, N, 128, 192, nullptr, 0);  // hW3
        run_gat(off, csr, N, 1, 128, G, att_src3, att_dst3, asrc, adst, Hh);           // aggr3
        run_split_bt(res3_w, whi, wlo, 192, 128, 192);
        run_gemm(b1hi, b1lo, whi, wlo, nullptr, b2hi, b2lo,
                 N, 128, 192, res3_b, 2, Hh, bias3);                                   // h3 -> split
    }

    // ---- MLP head ----
    {
        run_split_bt(mlp_w1, whi, wlo, 128, 64, 128);
        run_gemm(b2hi, b2lo, whi, wlo, J, nullptr, nullptr, N, 64, 128, mlp_b1, 1);
        mlp2_kernel<<<(N + 255) / 256, 256>>>(J, mlp_w2, mlp_b2, (float*)d_out, N);
    }
}